// round 14
// baseline (speedup 1.0000x reference)
#include <cuda_runtime.h>
#include <stdint.h>

// Fixed shape family: B=1, H=8, D=64. N, E read from in_sizes at launch.
#define H 8
#define D 64

// Scratch (allocation-free). All table values are POSITIVE floats, so raw
// IEEE bits order identically to unsigned ints -> no key transform anywhere.
static __device__ float        g_ea[1 << 22];  // exp(tanh(attn[n,h])) in (0.367, 2.72)
static __device__ unsigned int g_m [1 << 22];  // running max of ea bits; then 1/max after k_recip

// Fast tanh via hardware exp (MUFU.EX2): rel err ~1e-7.
__device__ __forceinline__ float fast_tanh(float x) {
    float e = __expf(2.0f * x);
    return 1.0f - __fdividef(2.0f, e + 1.0f);
}

// ── K1 (R6-EXACT config, 39.7us @ 66% DRAM — frozen): warp per 2 adjacent
// rows, 8 independent LDG.128/lane, W in 16 regs, streaming X loads,
// 1184 blocks x 256. f = 4*lo + 128k + j -> h = 2k + (lane>>4), d = 4*lo + j.
__global__ void k1_attn(const float4* __restrict__ X4, const float* __restrict__ Wk,
                        int N, int totalWarps) {
    int wid  = (blockIdx.x * blockDim.x + threadIdx.x) >> 5;
    int lane = threadIdx.x & 31;
    int lo = lane & 15, hi = lane >> 4;

    float w[4][4];
    #pragma unroll
    for (int k = 0; k < 4; k++)
        #pragma unroll
        for (int j = 0; j < 4; j++)
            w[k][j] = Wk[(4 * lo + j) * H + 2 * k + hi];

    for (int n = wid * 2; n < N; n += totalWarps * 2) {
        const float4* r0 = X4 + (size_t)n * (H * D / 4);
        bool two = (n + 1 < N);
        float4 v0[4], v1[4];
        #pragma unroll
        for (int k = 0; k < 4; k++) v0[k] = __ldcs(r0 + lane + 32 * k);
        if (two) {
            #pragma unroll
            for (int k = 0; k < 4; k++) v1[k] = __ldcs(r0 + 128 + lane + 32 * k);
        }
        float s0[4], s1[4];
        #pragma unroll
        for (int k = 0; k < 4; k++) {
            s0[k] = v0[k].x * w[k][0] + v0[k].y * w[k][1] + v0[k].z * w[k][2] + v0[k].w * w[k][3];
            s1[k] = two ? (v1[k].x * w[k][0] + v1[k].y * w[k][1] + v1[k].z * w[k][2] + v1[k].w * w[k][3]) : 0.0f;
        }
        #pragma unroll
        for (int o = 8; o >= 1; o >>= 1) {
            #pragma unroll
            for (int k = 0; k < 4; k++) {
                s0[k] += __shfl_xor_sync(0xffffffffu, s0[k], o);
                s1[k] += __shfl_xor_sync(0xffffffffu, s1[k], o);
            }
        }
        if (lo == 0) {
            float* ar = g_ea + (size_t)n * H;
            #pragma unroll
            for (int k = 0; k < 4; k++) ar[2 * k + hi] = __expf(fast_tanh(s0[k]));
            if (two) {
                #pragma unroll
                for (int k = 0; k < 4; k++) ar[H + 2 * k + hi] = __expf(fast_tanh(s1[k]));
            }
            if (hi == 0) {                     // re-init m to 0 (< any positive-float bits)
                uint4 z = make_uint4(0u, 0u, 0u, 0u);
                uint4* mz = (uint4*)(g_m + (size_t)n * H);
                mz[0] = z; mz[1] = z;
                if (two) { mz[2] = z; mz[3] = z; }
            }
        }
    }
}

// ── K2 (R11-EXACT, block 256 proven): 2 lanes per edge + ILP=2. Half-row
// LDG.128 gathers, atomicMax on raw positive-float bits, racy read-filter
// (stale-low reads only cost an extra atomic, never correctness).
__global__ void k2_max(const int* __restrict__ src, const int* __restrict__ tgt, int Ehalf) {
    int idx  = blockIdx.x * blockDim.x + threadIdx.x;
    int e0   = idx >> 1;
    int half = idx & 1;
    if (e0 >= Ehalf) return;
    int e1 = e0 + Ehalf;
    int s0 = __ldg(src + e0), t0 = __ldg(tgt + e0);
    int s1 = __ldg(src + e1), t1 = __ldg(tgt + e1);
    uint4 a0 = *(const uint4*)(g_ea + (size_t)s0 * H + half * 4);
    uint4 a1 = *(const uint4*)(g_ea + (size_t)s1 * H + half * 4);
    unsigned int* mp0 = g_m + (size_t)t0 * H + half * 4;
    unsigned int* mp1 = g_m + (size_t)t1 * H + half * 4;
    uint4 c0 = *(const uint4*)mp0;
    uint4 c1 = *(const uint4*)mp1;
    if (a0.x > c0.x) atomicMax(mp0 + 0, a0.x);
    if (a0.y > c0.y) atomicMax(mp0 + 1, a0.y);
    if (a0.z > c0.z) atomicMax(mp0 + 2, a0.z);
    if (a0.w > c0.w) atomicMax(mp0 + 3, a0.w);
    if (a1.x > c1.x) atomicMax(mp1 + 0, a1.x);
    if (a1.y > c1.y) atomicMax(mp1 + 1, a1.y);
    if (a1.z > c1.z) atomicMax(mp1 + 2, a1.z);
    if (a1.w > c1.w) atomicMax(mp1 + 3, a1.w);
}

// K2 tail for odd E.
__global__ void k2_tail(const int* __restrict__ src, const int* __restrict__ tgt,
                        int eStart, int E) {
    int idx  = blockIdx.x * blockDim.x + threadIdx.x;
    int e    = eStart + (idx >> 1);
    int half = idx & 1;
    if (e >= E) return;
    int s = __ldg(src + e), t = __ldg(tgt + e);
    uint4 a = *(const uint4*)(g_ea + (size_t)s * H + half * 4);
    unsigned int* mp = g_m + (size_t)t * H + half * 4;
    uint4 cur = *(const uint4*)mp;
    if (a.x > cur.x) atomicMax(mp + 0, a.x);
    if (a.y > cur.y) atomicMax(mp + 1, a.y);
    if (a.z > cur.z) atomicMax(mp + 2, a.z);
    if (a.w > cur.w) atomicMax(mp + 3, a.w);
}

// ── K2.5: per-NODE reciprocal of the max table in place (0.8M values, ~2us).
// Untargeted rows hold 1/0=inf (never gathered by K3).
__global__ void k_recip(int NH4) {
    int i = blockIdx.x * blockDim.x + threadIdx.x;
    if (i >= NH4) return;
    float4* p = (float4*)g_m + i;
    float4 v = *p;
    v.x = __fdividef(1.0f, v.x);
    v.y = __fdividef(1.0f, v.y);
    v.z = __fdividef(1.0f, v.z);
    v.w = __fdividef(1.0f, v.w);
    *p = v;
}

// ── K3: grid-stride + cross-iteration INDEX PREFETCH. Each thread walks
// (edge,half) slots with stride = gridDim*blockDim; while iteration i's
// gathers are in flight it issues iteration i+1's index loads, collapsing
// the serial idx->gather chain that left L1 25% idle in the one-shot form.
// Per-slot structure unchanged (proven ILP=2: edges e0 and e0+Ehalf,
// half-row LDG.128 gathers, contiguous drop/out). out = ea[src]*rm[tgt]*drop.
// (Reference denominator segment_max(exp(e-m))+1e-9 == 1.0f exactly in fp32.)
__global__ void k3_out(const int* __restrict__ src, const int* __restrict__ tgt,
                       const float4* __restrict__ drop4, float4* __restrict__ out4,
                       int Ehalf, int stride) {
    const int slots = Ehalf * 2;
    int idx = blockIdx.x * blockDim.x + threadIdx.x;
    if (idx >= slots) return;
    int e0 = idx >> 1, half = idx & 1, e1 = e0 + Ehalf;
    int s0 = __ldg(src + e0), t0 = __ldg(tgt + e0);
    int s1 = __ldg(src + e1), t1 = __ldg(tgt + e1);

    while (true) {
        // Issue current slot's 6 loads (all independent, indices resident).
        float4 a0 = *(const float4*)(g_ea + (size_t)s0 * H + half * 4);
        float4 a1 = *(const float4*)(g_ea + (size_t)s1 * H + half * 4);
        float4 r0 = *(const float4*)((const float*)g_m + (size_t)t0 * H + half * 4);
        float4 r1 = *(const float4*)((const float*)g_m + (size_t)t1 * H + half * 4);
        float4 d0 = __ldcs(drop4 + (size_t)e0 * 2 + half);
        float4 d1 = __ldcs(drop4 + (size_t)e1 * 2 + half);

        // Prefetch next slot's indices while the above are in flight.
        int nidx = idx + stride;
        bool more = nidx < slots;
        int ne0 = 0, nhalf = 0, ns0 = 0, nt0 = 0, ns1 = 0, nt1 = 0;
        if (more) {
            ne0 = nidx >> 1; nhalf = nidx & 1;
            ns0 = __ldg(src + ne0);         nt0 = __ldg(tgt + ne0);
            ns1 = __ldg(src + ne0 + Ehalf); nt1 = __ldg(tgt + ne0 + Ehalf);
        }

        float4 o0, o1;
        o0.x = a0.x * r0.x * d0.x;  o0.y = a0.y * r0.y * d0.y;
        o0.z = a0.z * r0.z * d0.z;  o0.w = a0.w * r0.w * d0.w;
        o1.x = a1.x * r1.x * d1.x;  o1.y = a1.y * r1.y * d1.y;
        o1.z = a1.z * r1.z * d1.z;  o1.w = a1.w * r1.w * d1.w;
        __stcs(out4 + (size_t)e0 * 2 + half, o0);
        __stcs(out4 + (size_t)e1 * 2 + half, o1);

        if (!more) break;
        idx = nidx; half = nhalf;
        e0 = ne0; e1 = ne0 + Ehalf;
        s0 = ns0; t0 = nt0; s1 = ns1; t1 = nt1;
    }
}

// K3 tail for odd E.
__global__ void k3_tail(const int* __restrict__ src, const int* __restrict__ tgt,
                        const float4* __restrict__ drop4, float4* __restrict__ out4,
                        int eStart, int E) {
    int idx  = blockIdx.x * blockDim.x + threadIdx.x;
    int e    = eStart + (idx >> 1);
    int half = idx & 1;
    if (e >= E) return;
    int s = __ldg(src + e), t = __ldg(tgt + e);
    float4 a = *(const float4*)(g_ea + (size_t)s * H + half * 4);
    float4 r = *(const float4*)((const float*)g_m + (size_t)t * H + half * 4);
    float4 d = __ldcs(drop4 + (size_t)e * 2 + half);
    float4 o;
    o.x = a.x * r.x * d.x;  o.y = a.y * r.y * d.y;
    o.z = a.z * r.z * d.z;  o.w = a.w * r.w * d.w;
    __stcs(out4 + (size_t)e * 2 + half, o);
}

// Inputs (metadata order): 0:X(f32) 1:attn_kernel(f32 D*H) 2:targets(i32 E)
// 3:sources(i32 E) 4:degree(f32 N, unused) 5:drop_mask(f32 E*H) 6:N.
extern "C" void kernel_launch(void* const* d_in, const int* in_sizes, int n_in,
                              void* d_out, int out_size) {
    const float4* X4   = (const float4*)d_in[0];
    const float*  Wk   = (const float*)d_in[1];
    const int*    tgt  = (const int*)d_in[2];
    const int*    srcs = (const int*)d_in[3];
    const float4* drop = (const float4*)d_in[5];
    float4*       out  = (float4*)d_out;

    const int E = in_sizes[2];
    const int N = in_sizes[4];

    // K1: R6-exact launch (proven optimum, frozen).
    const int k1_blocks = 1184;
    k1_attn<<<k1_blocks, 256>>>(X4, Wk, N, k1_blocks * (256 / 32));

    const int block = 256;
    const int Ehalf = E / 2;
    {   // K2: R11-exact (block 256, ILP=2)
        const int threads = Ehalf * 2;
        k2_max<<<(threads + block - 1) / block, block>>>(srcs, tgt, Ehalf);
        if (E & 1)
            k2_tail<<<1, 2>>>(srcs, tgt, Ehalf * 2, E);
    }

    const int NH4 = (N * H) / 4;
    k_recip<<<(NH4 + 255) / 256, 256>>>(NH4);

    {   // K3: grid-stride + index prefetch (888 blocks = ~6/SM)
        const int k3_blocks = 888;
        k3_out<<<k3_blocks, block>>>(srcs, tgt, drop, out, Ehalf, k3_blocks * block);
        if (E & 1)
            k3_tail<<<1, 2>>>(srcs, tgt, drop, out, Ehalf * 2, E);
    }
}

// round 15
// speedup vs baseline: 1.2708x; 1.2708x over previous
#include <cuda_runtime.h>
#include <stdint.h>

// Fixed shape family: B=1, H=8, D=64. N, E read from in_sizes at launch.
#define H 8
#define D 64

// Scratch (allocation-free). All table values are POSITIVE floats, so raw
// IEEE bits order identically to unsigned ints -> no key transform anywhere.
static __device__ float        g_ea[1 << 22];     // exp(tanh(attn[n,h]))
static __device__ unsigned int g_m [1 << 22];     // max of ea bits; 1/max after k_recip
static __device__ float4       g_eedge[1 << 23];  // per-EDGE ea rows (2 float4/edge), written by K2

// Fast tanh via hardware exp (MUFU.EX2): rel err ~1e-7.
__device__ __forceinline__ float fast_tanh(float x) {
    float e = __expf(2.0f * x);
    return 1.0f - __fdividef(2.0f, e + 1.0f);
}

// ── K1 (R6-EXACT config, 39.7us @ 66% DRAM — frozen): warp per 2 adjacent
// rows, 8 independent LDG.128/lane, W in 16 regs, streaming X loads,
// 1184 blocks x 256. f = 4*lo + 128k + j -> h = 2k + (lane>>4), d = 4*lo + j.
__global__ void k1_attn(const float4* __restrict__ X4, const float* __restrict__ Wk,
                        int N, int totalWarps) {
    int wid  = (blockIdx.x * blockDim.x + threadIdx.x) >> 5;
    int lane = threadIdx.x & 31;
    int lo = lane & 15, hi = lane >> 4;

    float w[4][4];
    #pragma unroll
    for (int k = 0; k < 4; k++)
        #pragma unroll
        for (int j = 0; j < 4; j++)
            w[k][j] = Wk[(4 * lo + j) * H + 2 * k + hi];

    for (int n = wid * 2; n < N; n += totalWarps * 2) {
        const float4* r0 = X4 + (size_t)n * (H * D / 4);
        bool two = (n + 1 < N);
        float4 v0[4], v1[4];
        #pragma unroll
        for (int k = 0; k < 4; k++) v0[k] = __ldcs(r0 + lane + 32 * k);
        if (two) {
            #pragma unroll
            for (int k = 0; k < 4; k++) v1[k] = __ldcs(r0 + 128 + lane + 32 * k);
        }
        float s0[4], s1[4];
        #pragma unroll
        for (int k = 0; k < 4; k++) {
            s0[k] = v0[k].x * w[k][0] + v0[k].y * w[k][1] + v0[k].z * w[k][2] + v0[k].w * w[k][3];
            s1[k] = two ? (v1[k].x * w[k][0] + v1[k].y * w[k][1] + v1[k].z * w[k][2] + v1[k].w * w[k][3]) : 0.0f;
        }
        #pragma unroll
        for (int o = 8; o >= 1; o >>= 1) {
            #pragma unroll
            for (int k = 0; k < 4; k++) {
                s0[k] += __shfl_xor_sync(0xffffffffu, s0[k], o);
                s1[k] += __shfl_xor_sync(0xffffffffu, s1[k], o);
            }
        }
        if (lo == 0) {
            float* ar = g_ea + (size_t)n * H;
            #pragma unroll
            for (int k = 0; k < 4; k++) ar[2 * k + hi] = __expf(fast_tanh(s0[k]));
            if (two) {
                #pragma unroll
                for (int k = 0; k < 4; k++) ar[H + 2 * k + hi] = __expf(fast_tanh(s1[k]));
            }
            if (hi == 0) {                     // re-init m to 0 (< any positive-float bits)
                uint4 z = make_uint4(0u, 0u, 0u, 0u);
                uint4* mz = (uint4*)(g_m + (size_t)n * H);
                mz[0] = z; mz[1] = z;
                if (two) { mz[2] = z; mz[3] = z; }
            }
        }
    }
}

// ── K2 (R11 structure + NEW: stores the gathered ea to an edge-ordered
// stream so K3 reads coalesced instead of gathering): 2 lanes per edge +
// ILP=2, half-row LDG.128 gathers, atomicMax on raw positive-float bits,
// racy read-filter (stale-low reads only cost an extra atomic).
__global__ void k2_max(const int* __restrict__ src, const int* __restrict__ tgt, int Ehalf) {
    int idx  = blockIdx.x * blockDim.x + threadIdx.x;
    int e0   = idx >> 1;
    int half = idx & 1;
    if (e0 >= Ehalf) return;
    int e1 = e0 + Ehalf;
    int s0 = __ldg(src + e0), t0 = __ldg(tgt + e0);
    int s1 = __ldg(src + e1), t1 = __ldg(tgt + e1);
    uint4 a0 = *(const uint4*)(g_ea + (size_t)s0 * H + half * 4);
    uint4 a1 = *(const uint4*)(g_ea + (size_t)s1 * H + half * 4);
    // Edge-ordered ea stream for K3 (coalesced STG.128 per thread).
    __stcs(&g_eedge[(size_t)e0 * 2 + half], make_float4(__uint_as_float(a0.x), __uint_as_float(a0.y),
                                                        __uint_as_float(a0.z), __uint_as_float(a0.w)));
    __stcs(&g_eedge[(size_t)e1 * 2 + half], make_float4(__uint_as_float(a1.x), __uint_as_float(a1.y),
                                                        __uint_as_float(a1.z), __uint_as_float(a1.w)));
    unsigned int* mp0 = g_m + (size_t)t0 * H + half * 4;
    unsigned int* mp1 = g_m + (size_t)t1 * H + half * 4;
    uint4 c0 = *(const uint4*)mp0;
    uint4 c1 = *(const uint4*)mp1;
    if (a0.x > c0.x) atomicMax(mp0 + 0, a0.x);
    if (a0.y > c0.y) atomicMax(mp0 + 1, a0.y);
    if (a0.z > c0.z) atomicMax(mp0 + 2, a0.z);
    if (a0.w > c0.w) atomicMax(mp0 + 3, a0.w);
    if (a1.x > c1.x) atomicMax(mp1 + 0, a1.x);
    if (a1.y > c1.y) atomicMax(mp1 + 1, a1.y);
    if (a1.z > c1.z) atomicMax(mp1 + 2, a1.z);
    if (a1.w > c1.w) atomicMax(mp1 + 3, a1.w);
}

// K2 tail for odd E (also writes the ea stream).
__global__ void k2_tail(const int* __restrict__ src, const int* __restrict__ tgt,
                        int eStart, int E) {
    int idx  = blockIdx.x * blockDim.x + threadIdx.x;
    int e    = eStart + (idx >> 1);
    int half = idx & 1;
    if (e >= E) return;
    int s = __ldg(src + e), t = __ldg(tgt + e);
    uint4 a = *(const uint4*)(g_ea + (size_t)s * H + half * 4);
    __stcs(&g_eedge[(size_t)e * 2 + half], make_float4(__uint_as_float(a.x), __uint_as_float(a.y),
                                                       __uint_as_float(a.z), __uint_as_float(a.w)));
    unsigned int* mp = g_m + (size_t)t * H + half * 4;
    uint4 cur = *(const uint4*)mp;
    if (a.x > cur.x) atomicMax(mp + 0, a.x);
    if (a.y > cur.y) atomicMax(mp + 1, a.y);
    if (a.z > cur.z) atomicMax(mp + 2, a.z);
    if (a.w > cur.w) atomicMax(mp + 3, a.w);
}

// ── K2.5: per-NODE reciprocal of the max table in place (0.8M values, ~2us).
// Untargeted rows hold 1/0=inf (never gathered by K3).
__global__ void k_recip(int NH4) {
    int i = blockIdx.x * blockDim.x + threadIdx.x;
    if (i >= NH4) return;
    float4* p = (float4*)g_m + i;
    float4 v = *p;
    v.x = __fdividef(1.0f, v.x);
    v.y = __fdividef(1.0f, v.y);
    v.z = __fdividef(1.0f, v.z);
    v.w = __fdividef(1.0f, v.w);
    *p = v;
}

// ── K3: 2 lanes per edge + ILP=2 (R11-proven one-shot massive-grid form).
// ea now read as a coalesced STREAM (written by K2) instead of a gather:
// warp wavefronts drop from ~42 to ~29 (one random gather left: rm[tgt]).
// out = ea_edge * rm[tgt] * drop, pure FMUL. (Reference denominator
// segment_max(exp(e-m))+1e-9 == 1.0f exactly in fp32, so it's a no-op.)
__global__ void k3_out(const int* __restrict__ tgt,
                       const float4* __restrict__ drop4, float4* __restrict__ out4,
                       int Ehalf) {
    int idx  = blockIdx.x * blockDim.x + threadIdx.x;
    int e0   = idx >> 1;
    int half = idx & 1;
    if (e0 >= Ehalf) return;
    int e1 = e0 + Ehalf;
    int t0 = __ldg(tgt + e0), t1 = __ldg(tgt + e1);
    float4 a0 = __ldcs(&g_eedge[(size_t)e0 * 2 + half]);
    float4 a1 = __ldcs(&g_eedge[(size_t)e1 * 2 + half]);
    float4 r0 = *(const float4*)((const float*)g_m + (size_t)t0 * H + half * 4);
    float4 r1 = *(const float4*)((const float*)g_m + (size_t)t1 * H + half * 4);
    float4 d0 = __ldcs(drop4 + (size_t)e0 * 2 + half);
    float4 d1 = __ldcs(drop4 + (size_t)e1 * 2 + half);
    float4 o0, o1;
    o0.x = a0.x * r0.x * d0.x;  o0.y = a0.y * r0.y * d0.y;
    o0.z = a0.z * r0.z * d0.z;  o0.w = a0.w * r0.w * d0.w;
    o1.x = a1.x * r1.x * d1.x;  o1.y = a1.y * r1.y * d1.y;
    o1.z = a1.z * r1.z * d1.z;  o1.w = a1.w * r1.w * d1.w;
    __stcs(out4 + (size_t)e0 * 2 + half, o0);
    __stcs(out4 + (size_t)e1 * 2 + half, o1);
}

// K3 tail for odd E.
__global__ void k3_tail(const int* __restrict__ tgt,
                        const float4* __restrict__ drop4, float4* __restrict__ out4,
                        int eStart, int E) {
    int idx  = blockIdx.x * blockDim.x + threadIdx.x;
    int e    = eStart + (idx >> 1);
    int half = idx & 1;
    if (e >= E) return;
    int t = __ldg(tgt + e);
    float4 a = __ldcs(&g_eedge[(size_t)e * 2 + half]);
    float4 r = *(const float4*)((const float*)g_m + (size_t)t * H + half * 4);
    float4 d = __ldcs(drop4 + (size_t)e * 2 + half);
    float4 o;
    o.x = a.x * r.x * d.x;  o.y = a.y * r.y * d.y;
    o.z = a.z * r.z * d.z;  o.w = a.w * r.w * d.w;
    __stcs(out4 + (size_t)e * 2 + half, o);
}

// Inputs (metadata order): 0:X(f32) 1:attn_kernel(f32 D*H) 2:targets(i32 E)
// 3:sources(i32 E) 4:degree(f32 N, unused) 5:drop_mask(f32 E*H) 6:N.
extern "C" void kernel_launch(void* const* d_in, const int* in_sizes, int n_in,
                              void* d_out, int out_size) {
    const float4* X4   = (const float4*)d_in[0];
    const float*  Wk   = (const float*)d_in[1];
    const int*    tgt  = (const int*)d_in[2];
    const int*    srcs = (const int*)d_in[3];
    const float4* drop = (const float4*)d_in[5];
    float4*       out  = (float4*)d_out;

    const int E = in_sizes[2];
    const int N = in_sizes[4];

    // K1: R6-exact launch (proven optimum, frozen).
    const int k1_blocks = 1184;
    k1_attn<<<k1_blocks, 256>>>(X4, Wk, N, k1_blocks * (256 / 32));

    const int block = 256;
    const int Ehalf = E / 2;
    {   // K2: R11 form + ea-stream store
        const int threads = Ehalf * 2;
        k2_max<<<(threads + block - 1) / block, block>>>(srcs, tgt, Ehalf);
        if (E & 1)
            k2_tail<<<1, 2>>>(srcs, tgt, Ehalf * 2, E);
    }

    const int NH4 = (N * H) / 4;
    k_recip<<<(NH4 + 255) / 256, 256>>>(NH4);

    {   // K3: one-shot massive grid, ILP=2, ea from stream
        const int threads = Ehalf * 2;
        k3_out<<<(threads + block - 1) / block, block>>>(tgt, drop, out, Ehalf);
        if (E & 1)
            k3_tail<<<1, 2>>>(tgt, drop, out, Ehalf * 2, E);
    }
}

// round 16
// speedup vs baseline: 1.4825x; 1.1666x over previous
#include <cuda_runtime.h>
#include <stdint.h>

// Fixed shape family: B=1, H=8, D=64. N, E read from in_sizes at launch.
#define H 8
#define D 64

// Scratch (allocation-free). All table values are POSITIVE floats, so raw
// IEEE bits order identically to unsigned ints -> no key transform anywhere.
static __device__ float        g_ea[1 << 22];  // exp(tanh(attn[n,h])) in (0.367, 2.72)
static __device__ unsigned int g_m [1 << 22];  // running max of ea bits; then 1/max after k_recip

// Fast tanh via hardware exp (MUFU.EX2): rel err ~1e-7.
__device__ __forceinline__ float fast_tanh(float x) {
    float e = __expf(2.0f * x);
    return 1.0f - __fdividef(2.0f, e + 1.0f);
}

__device__ __forceinline__ uint4 ldcg_u4(const unsigned int* p) {
    return __ldcg((const uint4*)p);
}
__device__ __forceinline__ float4 ldcg_f4(const float* p) {
    return __ldcg((const float4*)p);
}

// ── K1 (R6-EXACT config, 39.7us @ 66% DRAM — frozen): warp per 2 adjacent
// rows, 8 independent LDG.128/lane, W in 16 regs, streaming X loads,
// 1184 blocks x 256. f = 4*lo + 128k + j -> h = 2k + (lane>>4), d = 4*lo + j.
__global__ void k1_attn(const float4* __restrict__ X4, const float* __restrict__ Wk,
                        int N, int totalWarps) {
    int wid  = (blockIdx.x * blockDim.x + threadIdx.x) >> 5;
    int lane = threadIdx.x & 31;
    int lo = lane & 15, hi = lane >> 4;

    float w[4][4];
    #pragma unroll
    for (int k = 0; k < 4; k++)
        #pragma unroll
        for (int j = 0; j < 4; j++)
            w[k][j] = Wk[(4 * lo + j) * H + 2 * k + hi];

    for (int n = wid * 2; n < N; n += totalWarps * 2) {
        const float4* r0 = X4 + (size_t)n * (H * D / 4);
        bool two = (n + 1 < N);
        float4 v0[4], v1[4];
        #pragma unroll
        for (int k = 0; k < 4; k++) v0[k] = __ldcs(r0 + lane + 32 * k);
        if (two) {
            #pragma unroll
            for (int k = 0; k < 4; k++) v1[k] = __ldcs(r0 + 128 + lane + 32 * k);
        }
        float s0[4], s1[4];
        #pragma unroll
        for (int k = 0; k < 4; k++) {
            s0[k] = v0[k].x * w[k][0] + v0[k].y * w[k][1] + v0[k].z * w[k][2] + v0[k].w * w[k][3];
            s1[k] = two ? (v1[k].x * w[k][0] + v1[k].y * w[k][1] + v1[k].z * w[k][2] + v1[k].w * w[k][3]) : 0.0f;
        }
        #pragma unroll
        for (int o = 8; o >= 1; o >>= 1) {
            #pragma unroll
            for (int k = 0; k < 4; k++) {
                s0[k] += __shfl_xor_sync(0xffffffffu, s0[k], o);
                s1[k] += __shfl_xor_sync(0xffffffffu, s1[k], o);
            }
        }
        if (lo == 0) {
            float* ar = g_ea + (size_t)n * H;
            #pragma unroll
            for (int k = 0; k < 4; k++) ar[2 * k + hi] = __expf(fast_tanh(s0[k]));
            if (two) {
                #pragma unroll
                for (int k = 0; k < 4; k++) ar[H + 2 * k + hi] = __expf(fast_tanh(s1[k]));
            }
            if (hi == 0) {                     // re-init m to 0 (< any positive-float bits)
                uint4 z = make_uint4(0u, 0u, 0u, 0u);
                uint4* mz = (uint4*)(g_m + (size_t)n * H);
                mz[0] = z; mz[1] = z;
                if (two) { mz[2] = z; mz[3] = z; }
            }
        }
    }
}

// ── K2 (R11-EXACT structure; gathers now .cg = L2-only, random rows have no
// L1 reuse): 2 lanes per edge + ILP=2, half-row LDG.128 gathers, atomicMax
// on raw positive-float bits, racy read-filter (stale-low reads only cost
// an extra atomic, never correctness).
__global__ void k2_max(const int* __restrict__ src, const int* __restrict__ tgt, int Ehalf) {
    int idx  = blockIdx.x * blockDim.x + threadIdx.x;
    int e0   = idx >> 1;
    int half = idx & 1;
    if (e0 >= Ehalf) return;
    int e1 = e0 + Ehalf;
    int s0 = __ldg(src + e0), t0 = __ldg(tgt + e0);
    int s1 = __ldg(src + e1), t1 = __ldg(tgt + e1);
    uint4 a0 = ldcg_u4((const unsigned int*)g_ea + (size_t)s0 * H + half * 4);
    uint4 a1 = ldcg_u4((const unsigned int*)g_ea + (size_t)s1 * H + half * 4);
    unsigned int* mp0 = g_m + (size_t)t0 * H + half * 4;
    unsigned int* mp1 = g_m + (size_t)t1 * H + half * 4;
    uint4 c0 = ldcg_u4(mp0);
    uint4 c1 = ldcg_u4(mp1);
    if (a0.x > c0.x) atomicMax(mp0 + 0, a0.x);
    if (a0.y > c0.y) atomicMax(mp0 + 1, a0.y);
    if (a0.z > c0.z) atomicMax(mp0 + 2, a0.z);
    if (a0.w > c0.w) atomicMax(mp0 + 3, a0.w);
    if (a1.x > c1.x) atomicMax(mp1 + 0, a1.x);
    if (a1.y > c1.y) atomicMax(mp1 + 1, a1.y);
    if (a1.z > c1.z) atomicMax(mp1 + 2, a1.z);
    if (a1.w > c1.w) atomicMax(mp1 + 3, a1.w);
}

// K2 tail for odd E.
__global__ void k2_tail(const int* __restrict__ src, const int* __restrict__ tgt,
                        int eStart, int E) {
    int idx  = blockIdx.x * blockDim.x + threadIdx.x;
    int e    = eStart + (idx >> 1);
    int half = idx & 1;
    if (e >= E) return;
    int s = __ldg(src + e), t = __ldg(tgt + e);
    uint4 a = ldcg_u4((const unsigned int*)g_ea + (size_t)s * H + half * 4);
    unsigned int* mp = g_m + (size_t)t * H + half * 4;
    uint4 cur = ldcg_u4(mp);
    if (a.x > cur.x) atomicMax(mp + 0, a.x);
    if (a.y > cur.y) atomicMax(mp + 1, a.y);
    if (a.z > cur.z) atomicMax(mp + 2, a.z);
    if (a.w > cur.w) atomicMax(mp + 3, a.w);
}

// ── K2.5: per-NODE reciprocal of the max table in place (0.8M values, ~2us).
// Untargeted rows hold 1/0=inf (never gathered by K3).
__global__ void k_recip(int NH4) {
    int i = blockIdx.x * blockDim.x + threadIdx.x;
    if (i >= NH4) return;
    float4* p = (float4*)g_m + i;
    float4 v = *p;
    v.x = __fdividef(1.0f, v.x);
    v.y = __fdividef(1.0f, v.y);
    v.z = __fdividef(1.0f, v.z);
    v.w = __fdividef(1.0f, v.w);
    *p = v;
}

// ── K3 (R11-EXACT structure; gathers .cg): 2 lanes per edge + ILP=2, edges
// e0 and e0+Ehalf. out = ea[src]*rm[tgt]*drop, pure FMUL. (Reference
// denominator segment_max(exp(e-m))+1e-9 == 1.0f exactly in fp32: every
// segment attains exp(0)=1 and 1e-9 underflows the ulp of 1.0.)
__global__ void k3_out(const int* __restrict__ src, const int* __restrict__ tgt,
                       const float4* __restrict__ drop4, float4* __restrict__ out4,
                       int Ehalf) {
    int idx  = blockIdx.x * blockDim.x + threadIdx.x;
    int e0   = idx >> 1;
    int half = idx & 1;
    if (e0 >= Ehalf) return;
    int e1 = e0 + Ehalf;
    int s0 = __ldg(src + e0), t0 = __ldg(tgt + e0);
    int s1 = __ldg(src + e1), t1 = __ldg(tgt + e1);
    float4 a0 = ldcg_f4(g_ea + (size_t)s0 * H + half * 4);
    float4 a1 = ldcg_f4(g_ea + (size_t)s1 * H + half * 4);
    float4 r0 = ldcg_f4((const float*)g_m + (size_t)t0 * H + half * 4);
    float4 r1 = ldcg_f4((const float*)g_m + (size_t)t1 * H + half * 4);
    float4 d0 = __ldcs(drop4 + (size_t)e0 * 2 + half);
    float4 d1 = __ldcs(drop4 + (size_t)e1 * 2 + half);
    float4 o0, o1;
    o0.x = a0.x * r0.x * d0.x;  o0.y = a0.y * r0.y * d0.y;
    o0.z = a0.z * r0.z * d0.z;  o0.w = a0.w * r0.w * d0.w;
    o1.x = a1.x * r1.x * d1.x;  o1.y = a1.y * r1.y * d1.y;
    o1.z = a1.z * r1.z * d1.z;  o1.w = a1.w * r1.w * d1.w;
    __stcs(out4 + (size_t)e0 * 2 + half, o0);
    __stcs(out4 + (size_t)e1 * 2 + half, o1);
}

// K3 tail for odd E.
__global__ void k3_tail(const int* __restrict__ src, const int* __restrict__ tgt,
                        const float4* __restrict__ drop4, float4* __restrict__ out4,
                        int eStart, int E) {
    int idx  = blockIdx.x * blockDim.x + threadIdx.x;
    int e    = eStart + (idx >> 1);
    int half = idx & 1;
    if (e >= E) return;
    int s = __ldg(src + e), t = __ldg(tgt + e);
    float4 a = ldcg_f4(g_ea + (size_t)s * H + half * 4);
    float4 r = ldcg_f4((const float*)g_m + (size_t)t * H + half * 4);
    float4 d = __ldcs(drop4 + (size_t)e * 2 + half);
    float4 o;
    o.x = a.x * r.x * d.x;  o.y = a.y * r.y * d.y;
    o.z = a.z * r.z * d.z;  o.w = a.w * r.w * d.w;
    __stcs(out4 + (size_t)e * 2 + half, o);
}

// Inputs (metadata order): 0:X(f32) 1:attn_kernel(f32 D*H) 2:targets(i32 E)
// 3:sources(i32 E) 4:degree(f32 N, unused) 5:drop_mask(f32 E*H) 6:N.
extern "C" void kernel_launch(void* const* d_in, const int* in_sizes, int n_in,
                              void* d_out, int out_size) {
    const float4* X4   = (const float4*)d_in[0];
    const float*  Wk   = (const float*)d_in[1];
    const int*    tgt  = (const int*)d_in[2];
    const int*    srcs = (const int*)d_in[3];
    const float4* drop = (const float4*)d_in[5];
    float4*       out  = (float4*)d_out;

    const int E = in_sizes[2];
    const int N = in_sizes[4];

    // K1: R6-exact launch (proven optimum, frozen).
    const int k1_blocks = 1184;
    k1_attn<<<k1_blocks, 256>>>(X4, Wk, N, k1_blocks * (256 / 32));

    const int block = 256;
    const int Ehalf = E / 2;
    {   // K2: R11-exact (block 256, ILP=2)
        const int threads = Ehalf * 2;
        k2_max<<<(threads + block - 1) / block, block>>>(srcs, tgt, Ehalf);
        if (E & 1)
            k2_tail<<<1, 2>>>(srcs, tgt, Ehalf * 2, E);
    }

    const int NH4 = (N * H) / 4;
    k_recip<<<(NH4 + 255) / 256, 256>>>(NH4);

    {   // K3: R11-exact (block 256, ILP=2)
        const int threads = Ehalf * 2;
        k3_out<<<(threads + block - 1) / block, block>>>(srcs, tgt, drop, out, Ehalf);
        if (E & 1)
            k3_tail<<<1, 2>>>(srcs, tgt, drop, out, Ehalf * 2, E);
    }
}

// round 17
// speedup vs baseline: 1.4856x; 1.0021x over previous
#include <cuda_runtime.h>
#include <stdint.h>

// Fixed shape family: B=1, H=8, D=64. N, E read from in_sizes at launch.
#define H 8
#define D 64

// Scratch (allocation-free). All table values are POSITIVE floats, so raw
// IEEE bits order identically to unsigned ints -> no key transform anywhere.
static __device__ float        g_ea[1 << 22];  // exp(tanh(attn[n,h])) in (0.367, 2.72)
static __device__ unsigned int g_m [1 << 22];  // running max of ea bits; then 1/max after k_recip

// Fast tanh via hardware exp (MUFU.EX2): rel err ~1e-7.
__device__ __forceinline__ float fast_tanh(float x) {
    float e = __expf(2.0f * x);
    return 1.0f - __fdividef(2.0f, e + 1.0f);
}

// ── K1 (R6-EXACT config, 39.7us @ 66% DRAM — frozen after 5 failed
// structural experiments): warp per 2 adjacent rows, 8 independent
// LDG.128/lane, W in 16 regs, streaming X loads, 1184 blocks x 256.
// Element f = 4*lo + 128k + j -> h = 2k + (lane>>4), d = 4*lo + j.
__global__ void k1_attn(const float4* __restrict__ X4, const float* __restrict__ Wk,
                        int N, int totalWarps) {
    int wid  = (blockIdx.x * blockDim.x + threadIdx.x) >> 5;
    int lane = threadIdx.x & 31;
    int lo = lane & 15, hi = lane >> 4;

    float w[4][4];
    #pragma unroll
    for (int k = 0; k < 4; k++)
        #pragma unroll
        for (int j = 0; j < 4; j++)
            w[k][j] = Wk[(4 * lo + j) * H + 2 * k + hi];

    for (int n = wid * 2; n < N; n += totalWarps * 2) {
        const float4* r0 = X4 + (size_t)n * (H * D / 4);
        bool two = (n + 1 < N);
        float4 v0[4], v1[4];
        #pragma unroll
        for (int k = 0; k < 4; k++) v0[k] = __ldcs(r0 + lane + 32 * k);
        if (two) {
            #pragma unroll
            for (int k = 0; k < 4; k++) v1[k] = __ldcs(r0 + 128 + lane + 32 * k);
        }
        float s0[4], s1[4];
        #pragma unroll
        for (int k = 0; k < 4; k++) {
            s0[k] = v0[k].x * w[k][0] + v0[k].y * w[k][1] + v0[k].z * w[k][2] + v0[k].w * w[k][3];
            s1[k] = two ? (v1[k].x * w[k][0] + v1[k].y * w[k][1] + v1[k].z * w[k][2] + v1[k].w * w[k][3]) : 0.0f;
        }
        #pragma unroll
        for (int o = 8; o >= 1; o >>= 1) {
            #pragma unroll
            for (int k = 0; k < 4; k++) {
                s0[k] += __shfl_xor_sync(0xffffffffu, s0[k], o);
                s1[k] += __shfl_xor_sync(0xffffffffu, s1[k], o);
            }
        }
        if (lo == 0) {
            float* ar = g_ea + (size_t)n * H;
            #pragma unroll
            for (int k = 0; k < 4; k++) ar[2 * k + hi] = __expf(fast_tanh(s0[k]));
            if (two) {
                #pragma unroll
                for (int k = 0; k < 4; k++) ar[H + 2 * k + hi] = __expf(fast_tanh(s1[k]));
            }
            if (hi == 0) {                     // re-init m to 0 (< any positive-float bits)
                uint4 z = make_uint4(0u, 0u, 0u, 0u);
                uint4* mz = (uint4*)(g_m + (size_t)n * H);
                mz[0] = z; mz[1] = z;
                if (two) { mz[2] = z; mz[3] = z; }
            }
        }
    }
}

// ── K2 (R11-EXACT structure, plain gathers): 2 lanes per edge + ILP=2,
// half-row LDG.128 gathers (1 L1 wavefront per edge per table), atomicMax
// on raw positive-float bits, racy read-filter (stale-low reads only cost
// an extra atomic, never correctness).
__global__ void k2_max(const int* __restrict__ src, const int* __restrict__ tgt, int Ehalf) {
    int idx  = blockIdx.x * blockDim.x + threadIdx.x;
    int e0   = idx >> 1;
    int half = idx & 1;
    if (e0 >= Ehalf) return;
    int e1 = e0 + Ehalf;
    int s0 = __ldg(src + e0), t0 = __ldg(tgt + e0);
    int s1 = __ldg(src + e1), t1 = __ldg(tgt + e1);
    uint4 a0 = *(const uint4*)(g_ea + (size_t)s0 * H + half * 4);
    uint4 a1 = *(const uint4*)(g_ea + (size_t)s1 * H + half * 4);
    unsigned int* mp0 = g_m + (size_t)t0 * H + half * 4;
    unsigned int* mp1 = g_m + (size_t)t1 * H + half * 4;
    uint4 c0 = *(const uint4*)mp0;
    uint4 c1 = *(const uint4*)mp1;
    if (a0.x > c0.x) atomicMax(mp0 + 0, a0.x);
    if (a0.y > c0.y) atomicMax(mp0 + 1, a0.y);
    if (a0.z > c0.z) atomicMax(mp0 + 2, a0.z);
    if (a0.w > c0.w) atomicMax(mp0 + 3, a0.w);
    if (a1.x > c1.x) atomicMax(mp1 + 0, a1.x);
    if (a1.y > c1.y) atomicMax(mp1 + 1, a1.y);
    if (a1.z > c1.z) atomicMax(mp1 + 2, a1.z);
    if (a1.w > c1.w) atomicMax(mp1 + 3, a1.w);
}

// K2 tail for odd E.
__global__ void k2_tail(const int* __restrict__ src, const int* __restrict__ tgt,
                        int eStart, int E) {
    int idx  = blockIdx.x * blockDim.x + threadIdx.x;
    int e    = eStart + (idx >> 1);
    int half = idx & 1;
    if (e >= E) return;
    int s = __ldg(src + e), t = __ldg(tgt + e);
    uint4 a = *(const uint4*)(g_ea + (size_t)s * H + half * 4);
    unsigned int* mp = g_m + (size_t)t * H + half * 4;
    uint4 cur = *(const uint4*)mp;
    if (a.x > cur.x) atomicMax(mp + 0, a.x);
    if (a.y > cur.y) atomicMax(mp + 1, a.y);
    if (a.z > cur.z) atomicMax(mp + 2, a.z);
    if (a.w > cur.w) atomicMax(mp + 3, a.w);
}

// ── K2.5: per-NODE reciprocal of the max table in place (0.8M values, ~2us).
// Untargeted rows hold 1/0=inf (never gathered by K3).
__global__ void k_recip(int NH4) {
    int i = blockIdx.x * blockDim.x + threadIdx.x;
    if (i >= NH4) return;
    float4* p = (float4*)g_m + i;
    float4 v = *p;
    v.x = __fdividef(1.0f, v.x);
    v.y = __fdividef(1.0f, v.y);
    v.z = __fdividef(1.0f, v.z);
    v.w = __fdividef(1.0f, v.w);
    *p = v;
}

// ── K3 (R11-EXACT structure, plain gathers): 2 lanes per edge + ILP=2,
// edges e0 and e0+Ehalf. out = ea[src]*rm[tgt]*drop, pure FMUL. (Reference
// denominator segment_max(exp(e-m))+1e-9 == 1.0f exactly in fp32: every
// segment attains exp(0)=1 and 1e-9 underflows the ulp of 1.0.)
__global__ void k3_out(const int* __restrict__ src, const int* __restrict__ tgt,
                       const float4* __restrict__ drop4, float4* __restrict__ out4,
                       int Ehalf) {
    int idx  = blockIdx.x * blockDim.x + threadIdx.x;
    int e0   = idx >> 1;
    int half = idx & 1;
    if (e0 >= Ehalf) return;
    int e1 = e0 + Ehalf;
    int s0 = __ldg(src + e0), t0 = __ldg(tgt + e0);
    int s1 = __ldg(src + e1), t1 = __ldg(tgt + e1);
    float4 a0 = *(const float4*)(g_ea + (size_t)s0 * H + half * 4);
    float4 a1 = *(const float4*)(g_ea + (size_t)s1 * H + half * 4);
    float4 r0 = *(const float4*)((const float*)g_m + (size_t)t0 * H + half * 4);
    float4 r1 = *(const float4*)((const float*)g_m + (size_t)t1 * H + half * 4);
    float4 d0 = __ldcs(drop4 + (size_t)e0 * 2 + half);
    float4 d1 = __ldcs(drop4 + (size_t)e1 * 2 + half);
    float4 o0, o1;
    o0.x = a0.x * r0.x * d0.x;  o0.y = a0.y * r0.y * d0.y;
    o0.z = a0.z * r0.z * d0.z;  o0.w = a0.w * r0.w * d0.w;
    o1.x = a1.x * r1.x * d1.x;  o1.y = a1.y * r1.y * d1.y;
    o1.z = a1.z * r1.z * d1.z;  o1.w = a1.w * r1.w * d1.w;
    __stcs(out4 + (size_t)e0 * 2 + half, o0);
    __stcs(out4 + (size_t)e1 * 2 + half, o1);
}

// K3 tail for odd E.
__global__ void k3_tail(const int* __restrict__ src, const int* __restrict__ tgt,
                        const float4* __restrict__ drop4, float4* __restrict__ out4,
                        int eStart, int E) {
    int idx  = blockIdx.x * blockDim.x + threadIdx.x;
    int e    = eStart + (idx >> 1);
    int half = idx & 1;
    if (e >= E) return;
    int s = __ldg(src + e), t = __ldg(tgt + e);
    float4 a = *(const float4*)(g_ea + (size_t)s * H + half * 4);
    float4 r = *(const float4*)((const float*)g_m + (size_t)t * H + half * 4);
    float4 d = __ldcs(drop4 + (size_t)e * 2 + half);
    float4 o;
    o.x = a.x * r.x * d.x;  o.y = a.y * r.y * d.y;
    o.z = a.z * r.z * d.z;  o.w = a.w * r.w * d.w;
    __stcs(out4 + (size_t)e * 2 + half, o);
}

// Inputs (metadata order): 0:X(f32) 1:attn_kernel(f32 D*H) 2:targets(i32 E)
// 3:sources(i32 E) 4:degree(f32 N, unused) 5:drop_mask(f32 E*H) 6:N.
extern "C" void kernel_launch(void* const* d_in, const int* in_sizes, int n_in,
                              void* d_out, int out_size) {
    const float4* X4   = (const float4*)d_in[0];
    const float*  Wk   = (const float*)d_in[1];
    const int*    tgt  = (const int*)d_in[2];
    const int*    srcs = (const int*)d_in[3];
    const float4* drop = (const float4*)d_in[5];
    float4*       out  = (float4*)d_out;

    const int E = in_sizes[2];
    const int N = in_sizes[4];

    // K1: R6-exact launch (proven optimum, frozen).
    const int k1_blocks = 1184;
    k1_attn<<<k1_blocks, 256>>>(X4, Wk, N, k1_blocks * (256 / 32));

    // Edge kernels: R11 structure, block 128 (last unexplored launch axis).
    const int block = 128;
    const int Ehalf = E / 2;
    {
        const int threads = Ehalf * 2;
        k2_max<<<(threads + block - 1) / block, block>>>(srcs, tgt, Ehalf);
        if (E & 1)
            k2_tail<<<1, 2>>>(srcs, tgt, Ehalf * 2, E);
    }

    const int NH4 = (N * H) / 4;
    k_recip<<<(NH4 + 255) / 256, 256>>>(NH4);

    {
        const int threads = Ehalf * 2;
        k3_out<<<(threads + block - 1) / block, block>>>(srcs, tgt, drop, out, Ehalf);
        if (E & 1)
            k3_tail<<<1, 2>>>(srcs, tgt, drop, out, Ehalf * 2, E);
    }
}